// round 15
// baseline (speedup 1.0000x reference)
#include <cuda_runtime.h>
#include <cuda_fp16.h>
#include <cstdint>

// Problem constants
#define T_TOK 2048
#define HID   2048
#define INTER 768
#define NEXP  8
#define BK    32
#define SAH   40          // smem row stride in halves (conflict-free frags)
#define STAGE_H (128 * SAH)

// Static device scratch
__device__ int    g_cnt[NEXP];
__device__ int    g_tok[NEXP * T_TOK];                    // packed t*2 + slot
__device__ float  g_wt [NEXP * T_TOK];
__device__ __half g_xh [(size_t)T_TOK * HID];             // x fp16
__device__ __half g_wgu[(size_t)NEXP * 2 * INTER * HID];  // [e][ng][k] interleaved g/u
__device__ __half g_wdt[(size_t)NEXP * HID * INTER];      // [e][n][k]
__device__ __half g_hc [(size_t)NEXP * T_TOK * INTER];    // compacted h fp16
__device__ float  g_y  [2ull * T_TOK * HID];              // per-slot outputs

// ---------------------------------------------------------------------------
__device__ __forceinline__ void mma_f16(float* d, const unsigned* a, const unsigned* b) {
    asm volatile(
        "mma.sync.aligned.m16n8k16.row.col.f32.f16.f16.f32 "
        "{%0,%1,%2,%3},{%4,%5,%6,%7},{%8,%9},{%0,%1,%2,%3};"
        : "+f"(d[0]), "+f"(d[1]), "+f"(d[2]), "+f"(d[3])
        : "r"(a[0]), "r"(a[1]), "r"(a[2]), "r"(a[3]), "r"(b[0]), "r"(b[1]));
}
__device__ __forceinline__ void cp_async16(void* smem, const void* gmem) {
    unsigned s = (unsigned)__cvta_generic_to_shared(smem);
    asm volatile("cp.async.cg.shared.global [%0], [%1], 16;" :: "r"(s), "l"(gmem));
}
#define CP_COMMIT() asm volatile("cp.async.commit_group;")
#define CP_WAIT(n)  asm volatile("cp.async.wait_group %0;" :: "n"(n))

// ---------------------------------------------------------------------------
// preprocessing: x -> fp16 (+ zero counters)
// ---------------------------------------------------------------------------
__global__ void cvt_x_kernel(const float* __restrict__ x) {
    int i = blockIdx.x * blockDim.x + threadIdx.x;   // 8 floats per thread
    size_t o = (size_t)i * 8;
    float4 v0 = *reinterpret_cast<const float4*>(x + o);
    float4 v1 = *reinterpret_cast<const float4*>(x + o + 4);
    __align__(16) __half2 h[4];
    h[0] = __floats2half2_rn(v0.x, v0.y);
    h[1] = __floats2half2_rn(v0.z, v0.w);
    h[2] = __floats2half2_rn(v1.x, v1.y);
    h[3] = __floats2half2_rn(v1.z, v1.w);
    *reinterpret_cast<uint4*>(&g_xh[o]) = *reinterpret_cast<uint4*>(h);
    if (blockIdx.x == 0 && threadIdx.x < NEXP) g_cnt[threadIdx.x] = 0;
}

// ---------------------------------------------------------------------------
// Wg/Wu [e][k=HID][n=INTER] -> g_wgu [e][ng][k] fp16, ng = (n/8)*16 + n%8 (+8 for up)
// tile: 32 k x 32 n, block 256
// ---------------------------------------------------------------------------
__global__ __launch_bounds__(256) void cvt_wgu_kernel(const float* __restrict__ Wg,
                                                      const float* __restrict__ Wu) {
    const int e = blockIdx.z, k0 = blockIdx.y * 32, n0 = blockIdx.x * 32;
    __shared__ float sg[32][33], su[32][33];
    const int tid = threadIdx.x;
    const int r = tid >> 3, cq = (tid & 7) * 4;
    {
        size_t off = ((size_t)e * HID + k0 + r) * INTER + n0 + cq;
        float4 vg = *reinterpret_cast<const float4*>(Wg + off);
        float4 vu = *reinterpret_cast<const float4*>(Wu + off);
        sg[r][cq + 0] = vg.x; sg[r][cq + 1] = vg.y; sg[r][cq + 2] = vg.z; sg[r][cq + 3] = vg.w;
        su[r][cq + 0] = vu.x; su[r][cq + 1] = vu.y; su[r][cq + 2] = vu.z; su[r][cq + 3] = vu.w;
    }
    __syncthreads();
    const int o = tid >> 2, c = (tid & 3) * 8;
    const int w = o & 15;
    const int nl = ((o >> 4) << 3) + (w & 7);
    const bool isU = (w >= 8);
    __align__(16) __half hh[8];
#pragma unroll
    for (int i = 0; i < 8; i++)
        hh[i] = __float2half(isU ? su[c + i][nl] : sg[c + i][nl]);
    *reinterpret_cast<uint4*>(&g_wgu[((size_t)e * 2 * INTER + n0 * 2 + o) * HID + k0 + c]) =
        *reinterpret_cast<uint4*>(hh);
}

// ---------------------------------------------------------------------------
// Wd [e][k=INTER][n=HID] -> g_wdt [e][n][k] fp16. tile: 32 k x 64 n, block 256
// ---------------------------------------------------------------------------
__global__ __launch_bounds__(256) void cvt_wd_kernel(const float* __restrict__ Wd) {
    const int e = blockIdx.z, k0 = blockIdx.y * 32, n0 = blockIdx.x * 64;
    __shared__ float sd[32][65];
    const int tid = threadIdx.x;
    const int r = tid >> 3, cq = (tid & 7) * 8;
    {
        size_t off = ((size_t)e * INTER + k0 + r) * HID + n0 + cq;
        float4 v0 = *reinterpret_cast<const float4*>(Wd + off);
        float4 v1 = *reinterpret_cast<const float4*>(Wd + off + 4);
        sd[r][cq + 0] = v0.x; sd[r][cq + 1] = v0.y; sd[r][cq + 2] = v0.z; sd[r][cq + 3] = v0.w;
        sd[r][cq + 4] = v1.x; sd[r][cq + 5] = v1.y; sd[r][cq + 6] = v1.z; sd[r][cq + 7] = v1.w;
    }
    __syncthreads();
    const int o = tid >> 2, c = (tid & 3) * 8;
    __align__(16) __half hh[8];
#pragma unroll
    for (int i = 0; i < 8; i++)
        hh[i] = __float2half(sd[c + i][o]);
    *reinterpret_cast<uint4*>(&g_wdt[((size_t)e * HID + n0 + o) * INTER + k0 + c]) =
        *reinterpret_cast<uint4*>(hh);
}

// ---------------------------------------------------------------------------
// router (exact fp32); packs slot bit into g_tok
// ---------------------------------------------------------------------------
__global__ __launch_bounds__(128) void router_kernel(const float* __restrict__ x,
                                                     const float* __restrict__ wgate) {
    const int t = blockIdx.x;
    const int tid = threadIdx.x;
    const float* xr = x + (size_t)t * HID;

    float part[NEXP];
#pragma unroll
    for (int e = 0; e < NEXP; e++) part[e] = 0.f;

    for (int h = tid * 4; h < HID; h += 128 * 4) {
        float4 xv = *reinterpret_cast<const float4*>(xr + h);
#pragma unroll
        for (int e = 0; e < NEXP; e++) {
            float4 wv = *reinterpret_cast<const float4*>(wgate + e * HID + h);
            part[e] += xv.x * wv.x + xv.y * wv.y + xv.z * wv.z + xv.w * wv.w;
        }
    }
#pragma unroll
    for (int e = 0; e < NEXP; e++)
#pragma unroll
        for (int o = 16; o > 0; o >>= 1)
            part[e] += __shfl_xor_sync(0xffffffffu, part[e], o);

    __shared__ float wsum[4][NEXP];
    const int warp = tid >> 5, lane = tid & 31;
    if (lane == 0)
#pragma unroll
        for (int e = 0; e < NEXP; e++) wsum[warp][e] = part[e];
    __syncthreads();

    if (tid == 0) {
        float logits[NEXP];
#pragma unroll
        for (int e = 0; e < NEXP; e++)
            logits[e] = wsum[0][e] + wsum[1][e] + wsum[2][e] + wsum[3][e];

        float mx = logits[0];
#pragma unroll
        for (int e = 1; e < NEXP; e++) mx = fmaxf(mx, logits[e]);
        float p[NEXP], s = 0.f;
#pragma unroll
        for (int e = 0; e < NEXP; e++) { p[e] = expf(logits[e] - mx); s += p[e]; }
        float inv = 1.f / s;
#pragma unroll
        for (int e = 0; e < NEXP; e++) p[e] *= inv;

        int e1 = 0;
#pragma unroll
        for (int e = 1; e < NEXP; e++) if (p[e] > p[e1]) e1 = e;
        int e2 = (e1 == 0) ? 1 : 0;
#pragma unroll
        for (int e = 0; e < NEXP; e++)
            if (e != e1 && p[e] > p[e2]) e2 = e;

        float w1 = p[e1], w2 = p[e2];
        float rs = 1.f / (w1 + w2);
        w1 *= rs; w2 *= rs;

        int s1 = atomicAdd(&g_cnt[e1], 1);
        g_tok[e1 * T_TOK + s1] = t * 2;         // slot 0
        g_wt [e1 * T_TOK + s1] = w1;
        int s2 = atomicAdd(&g_cnt[e2], 1);
        g_tok[e2 * T_TOK + s2] = t * 2 + 1;     // slot 1
        g_wt [e2 * T_TOK + s2] = w2;
    }
}

// ---------------------------------------------------------------------------
// gemm1: block 128m x 128ng (=64 logical n, g/u interleaved), 8 warps 64x32,
// 4-stage pure cp.async pipeline; silu(g)*u*w epilogue -> g_hc fp16
// ---------------------------------------------------------------------------
__global__ __launch_bounds__(256) void gemm1_kernel() {
    const int e = blockIdx.z;
    const int rows = g_cnt[e];
    const int m0 = blockIdx.y * 128;
    if (m0 >= rows) return;
    const int ngb = blockIdx.x * 128;
    const int n0l = blockIdx.x * 64;

    extern __shared__ __align__(16) __half dsm[];
    __half* sA = dsm;                   // 4 stages
    __half* sB = dsm + 4 * STAGE_H;     // 4 stages

    __shared__ int   stok[128];
    __shared__ float swt[128];

    const int tid = threadIdx.x;
    if (tid < 128) {
        int gm = m0 + tid;
        int idx = (gm < rows) ? gm : (rows - 1);
        stok[tid] = g_tok[e * T_TOK + idx] >> 1;
        swt [tid] = (gm < rows) ? g_wt[e * T_TOK + gm] : 0.f;
    }
    __syncthreads();

    const int lr = tid >> 1;             // loader row 0..127
    const int lo = (tid & 1) * 16;       // half-offset 0 or 16
    const __half* asrc = g_xh + (size_t)stok[lr] * HID + lo;
    const __half* bsrc = g_wgu + ((size_t)e * 2 * INTER + ngb + lr) * HID + lo;

    const int NT = HID / BK;   // 64

    auto issue = [&](int t) {
        if (t < NT) {
            __half* A = sA + (t & 3) * STAGE_H;
            __half* B = sB + (t & 3) * STAGE_H;
            int kk = t * BK;
            cp_async16(&A[lr * SAH + lo],     asrc + kk);
            cp_async16(&A[lr * SAH + lo + 8], asrc + kk + 8);
            cp_async16(&B[lr * SAH + lo],     bsrc + kk);
            cp_async16(&B[lr * SAH + lo + 8], bsrc + kk + 8);
        }
        CP_COMMIT();
    };

    issue(0); issue(1); issue(2);

    const int lane = tid & 31;
    const int warp = tid >> 5;
    const int wm = (warp & 1) * 64;
    const int wn = (warp >> 1) * 32;
    const int gid = lane >> 2, tg = lane & 3;

    float acc[4][4][4] = {};

    for (int t = 0; t < NT; t++) {
        CP_WAIT(2);
        __syncthreads();          // stage t visible; compute(t-1) done -> (t+3)&3 free
        issue(t + 3);

        const __half* A = sA + (t & 3) * STAGE_H;
        const __half* B = sB + (t & 3) * STAGE_H;

#pragma unroll
        for (int ks = 0; ks < BK; ks += 16) {
            unsigned a[4][4];
#pragma unroll
            for (int f = 0; f < 4; f++) {
                int r0 = wm + f * 16 + gid;
                a[f][0] = *reinterpret_cast<const unsigned*>(&A[(r0    ) * SAH + ks + 2 * tg    ]);
                a[f][1] = *reinterpret_cast<const unsigned*>(&A[(r0 + 8) * SAH + ks + 2 * tg    ]);
                a[f][2] = *reinterpret_cast<const unsigned*>(&A[(r0    ) * SAH + ks + 2 * tg + 8]);
                a[f][3] = *reinterpret_cast<const unsigned*>(&A[(r0 + 8) * SAH + ks + 2 * tg + 8]);
            }
            unsigned b[4][2];
#pragma unroll
            for (int j = 0; j < 4; j++) {
                int c = wn + j * 8 + gid;
                b[j][0] = *reinterpret_cast<const unsigned*>(&B[c * SAH + ks + 2 * tg    ]);
                b[j][1] = *reinterpret_cast<const unsigned*>(&B[c * SAH + ks + 2 * tg + 8]);
            }
#pragma unroll
            for (int f = 0; f < 4; f++)
#pragma unroll
                for (int j = 0; j < 4; j++)
                    mma_f16(acc[f][j], a[f], b[j]);
        }
    }

    // epilogue: j even = gate group, j odd = up group of same 8 logical cols
    __half* hbase = g_hc + (size_t)e * T_TOK * INTER;
#pragma unroll
    for (int f = 0; f < 4; f++) {
#pragma unroll
        for (int half = 0; half < 2; half++) {
            int rm = wm + f * 16 + half * 8 + gid;
            int gm = m0 + rm;
            if (gm < rows) {
                float w = swt[rm];
#pragma unroll
                for (int p = 0; p < 2; p++) {
                    float g0 = acc[f][2 * p    ][half * 2 + 0];
                    float g1 = acc[f][2 * p    ][half * 2 + 1];
                    float u0 = acc[f][2 * p + 1][half * 2 + 0];
                    float u1 = acc[f][2 * p + 1][half * 2 + 1];
                    float s0 = g0 / (1.f + expf(-g0)) * u0 * w;
                    float s1 = g1 / (1.f + expf(-g1)) * u1 * w;
                    int col = n0l + (wn >> 1) + p * 8 + 2 * tg;
                    *reinterpret_cast<__half2*>(hbase + (size_t)gm * INTER + col) =
                        __floats2half2_rn(s0, s1);
                }
            }
        }
    }
}

// ---------------------------------------------------------------------------
// gemm2: block 128m x 128n, 8 warps 64x32, 4-stage cp.async, STG to slot buf
// ---------------------------------------------------------------------------
__global__ __launch_bounds__(256) void gemm2_kernel() {
    const int e = blockIdx.z;
    const int rows = g_cnt[e];
    const int m0 = blockIdx.y * 128;
    if (m0 >= rows) return;
    const int n0 = blockIdx.x * 128;

    extern __shared__ __align__(16) __half dsm[];
    __half* sA = dsm;
    __half* sB = dsm + 4 * STAGE_H;

    __shared__ int stok[128];

    const int tid = threadIdx.x;
    if (tid < 128) {
        int gm = m0 + tid;
        int idx = (gm < rows) ? gm : (rows - 1);
        stok[tid] = g_tok[e * T_TOK + idx];   // packed
    }
    __syncthreads();

    const int lr = tid >> 1;
    const int lo = (tid & 1) * 16;
    int aidx = m0 + lr;
    if (aidx >= rows) aidx = rows - 1;
    const __half* asrc = g_hc + ((size_t)e * T_TOK + aidx) * INTER + lo;
    const __half* bsrc = g_wdt + ((size_t)e * HID + n0 + lr) * INTER + lo;

    const int NT = INTER / BK;   // 24

    auto issue = [&](int t) {
        if (t < NT) {
            __half* A = sA + (t & 3) * STAGE_H;
            __half* B = sB + (t & 3) * STAGE_H;
            int kk = t * BK;
            cp_async16(&A[lr * SAH + lo],     asrc + kk);
            cp_async16(&A[lr * SAH + lo + 8], asrc + kk + 8);
            cp_async16(&B[lr * SAH + lo],     bsrc + kk);
            cp_async16(&B[lr * SAH + lo + 8], bsrc + kk + 8);
        }
        CP_COMMIT();
    };

    issue(0); issue(1); issue(2);

    const int lane = tid & 31;
    const int warp = tid >> 5;
    const int wm = (warp & 1) * 64;
    const int wn = (warp >> 1) * 32;
    const int gid = lane >> 2, tg = lane & 3;

    float acc[4][4][4] = {};

    for (int t = 0; t < NT; t++) {
        CP_WAIT(2);
        __syncthreads();
        issue(t + 3);

        const __half* A = sA + (t & 3) * STAGE_H;
        const __half* B = sB + (t & 3) * STAGE_H;

#pragma unroll
        for (int ks = 0; ks < BK; ks += 16) {
            unsigned a[4][4];
#pragma unroll
            for (int f = 0; f < 4; f++) {
                int r0 = wm + f * 16 + gid;
                a[f][0] = *reinterpret_cast<const unsigned*>(&A[(r0    ) * SAH + ks + 2 * tg    ]);
                a[f][1] = *reinterpret_cast<const unsigned*>(&A[(r0 + 8) * SAH + ks + 2 * tg    ]);
                a[f][2] = *reinterpret_cast<const unsigned*>(&A[(r0    ) * SAH + ks + 2 * tg + 8]);
                a[f][3] = *reinterpret_cast<const unsigned*>(&A[(r0 + 8) * SAH + ks + 2 * tg + 8]);
            }
            unsigned b[4][2];
#pragma unroll
            for (int j = 0; j < 4; j++) {
                int c = wn + j * 8 + gid;
                b[j][0] = *reinterpret_cast<const unsigned*>(&B[c * SAH + ks + 2 * tg    ]);
                b[j][1] = *reinterpret_cast<const unsigned*>(&B[c * SAH + ks + 2 * tg + 8]);
            }
#pragma unroll
            for (int f = 0; f < 4; f++)
#pragma unroll
                for (int j = 0; j < 4; j++)
                    mma_f16(acc[f][j], a[f], b[j]);
        }
    }

#pragma unroll
    for (int f = 0; f < 4; f++) {
#pragma unroll
        for (int half = 0; half < 2; half++) {
            int rm = wm + f * 16 + half * 8 + gid;
            int gm = m0 + rm;
            if (gm < rows) {
                int v = stok[rm];
                float* orow = g_y + (size_t)(v & 1) * T_TOK * HID + (size_t)(v >> 1) * HID + n0;
#pragma unroll
                for (int j = 0; j < 4; j++) {
                    int col = wn + j * 8 + 2 * tg;
                    *reinterpret_cast<float2*>(orow + col) =
                        make_float2(acc[f][j][half * 2 + 0], acc[f][j][half * 2 + 1]);
                }
            }
        }
    }
}

// ---------------------------------------------------------------------------
// combine: out = y_slot0 + y_slot1 (fully overwrites out)
// ---------------------------------------------------------------------------
__global__ void combine_kernel(float* __restrict__ out) {
    int i = blockIdx.x * blockDim.x + threadIdx.x;
    float4 a = reinterpret_cast<const float4*>(g_y)[i];
    float4 b = reinterpret_cast<const float4*>(g_y + (size_t)T_TOK * HID)[i];
    reinterpret_cast<float4*>(out)[i] = make_float4(a.x + b.x, a.y + b.y, a.z + b.z, a.w + b.w);
}

// ---------------------------------------------------------------------------
extern "C" void kernel_launch(void* const* d_in, const int* in_sizes, int n_in,
                              void* d_out, int out_size) {
    const float* x     = (const float*)d_in[0];
    const float* wgate = (const float*)d_in[1];
    const float* Wg    = (const float*)d_in[2];
    const float* Wu    = (const float*)d_in[3];
    const float* Wd    = (const float*)d_in[4];
    float* out = (float*)d_out;

    const int gsmem = 8 * STAGE_H * (int)sizeof(__half);   // 81920
    cudaFuncSetAttribute(gemm1_kernel, cudaFuncAttributeMaxDynamicSharedMemorySize, gsmem);
    cudaFuncSetAttribute(gemm2_kernel, cudaFuncAttributeMaxDynamicSharedMemorySize, gsmem);

    cvt_x_kernel<<<(T_TOK * HID / 8 + 255) / 256, 256>>>(x);
    cvt_wgu_kernel<<<dim3(INTER / 32, HID / 32, NEXP), 256>>>(Wg, Wu);
    cvt_wd_kernel<<<dim3(HID / 64, INTER / 32, NEXP), 256>>>(Wd);

    router_kernel<<<T_TOK, 128>>>(x, wgate);

    gemm1_kernel<<<dim3(INTER / 64, T_TOK / 128, NEXP), 256, gsmem>>>();
    gemm2_kernel<<<dim3(HID / 128, T_TOK / 128, NEXP), 256, gsmem>>>();

    combine_kernel<<<(T_TOK * HID / 4 + 255) / 256, 256>>>(out);
}

// round 16
// speedup vs baseline: 1.0068x; 1.0068x over previous
#include <cuda_runtime.h>
#include <cuda_fp16.h>
#include <cstdint>

// Problem constants
#define T_TOK 2048
#define HID   2048
#define INTER 768
#define NEXP  8
#define BK    32
#define SAH   40          // smem row stride in halves (conflict-free frags)
#define STAGE_H (128 * SAH)

// Static device scratch
__device__ int    g_cnt[NEXP];
__device__ int    g_tok[NEXP * T_TOK];                    // packed t*2 + slot
__device__ float  g_wt [NEXP * T_TOK];
__device__ __half g_xh [(size_t)T_TOK * HID];             // x fp16
__device__ __half g_wgu[(size_t)NEXP * 2 * INTER * HID];  // [e][ng][k] interleaved g/u
__device__ __half g_wdt[(size_t)NEXP * HID * INTER];      // [e][n][k]
__device__ __half g_hc [(size_t)NEXP * T_TOK * INTER];    // compacted h fp16
__device__ float  g_y  [2ull * T_TOK * HID];              // per-slot outputs

// ---------------------------------------------------------------------------
__device__ __forceinline__ void mma_f16(float* d, const unsigned* a, const unsigned* b) {
    asm volatile(
        "mma.sync.aligned.m16n8k16.row.col.f32.f16.f16.f32 "
        "{%0,%1,%2,%3},{%4,%5,%6,%7},{%8,%9},{%0,%1,%2,%3};"
        : "+f"(d[0]), "+f"(d[1]), "+f"(d[2]), "+f"(d[3])
        : "r"(a[0]), "r"(a[1]), "r"(a[2]), "r"(a[3]), "r"(b[0]), "r"(b[1]));
}
__device__ __forceinline__ void cp_async16(void* smem, const void* gmem) {
    unsigned s = (unsigned)__cvta_generic_to_shared(smem);
    asm volatile("cp.async.cg.shared.global [%0], [%1], 16;" :: "r"(s), "l"(gmem));
}
#define CP_COMMIT() asm volatile("cp.async.commit_group;")
#define CP_WAIT(n)  asm volatile("cp.async.wait_group %0;" :: "n"(n))

// ---------------------------------------------------------------------------
// preprocessing: x -> fp16 (+ zero counters)
// ---------------------------------------------------------------------------
__global__ void cvt_x_kernel(const float* __restrict__ x) {
    int i = blockIdx.x * blockDim.x + threadIdx.x;   // 8 floats per thread
    size_t o = (size_t)i * 8;
    float4 v0 = *reinterpret_cast<const float4*>(x + o);
    float4 v1 = *reinterpret_cast<const float4*>(x + o + 4);
    __align__(16) __half2 h[4];
    h[0] = __floats2half2_rn(v0.x, v0.y);
    h[1] = __floats2half2_rn(v0.z, v0.w);
    h[2] = __floats2half2_rn(v1.x, v1.y);
    h[3] = __floats2half2_rn(v1.z, v1.w);
    *reinterpret_cast<uint4*>(&g_xh[o]) = *reinterpret_cast<uint4*>(h);
    if (blockIdx.x == 0 && threadIdx.x < NEXP) g_cnt[threadIdx.x] = 0;
}

// ---------------------------------------------------------------------------
// Wg/Wu [e][k=HID][n=INTER] -> g_wgu [e][ng][k] fp16, ng = (n/8)*16 + n%8 (+8 for up)
// tile: 32 k x 32 n, block 256
// ---------------------------------------------------------------------------
__global__ __launch_bounds__(256) void cvt_wgu_kernel(const float* __restrict__ Wg,
                                                      const float* __restrict__ Wu) {
    const int e = blockIdx.z, k0 = blockIdx.y * 32, n0 = blockIdx.x * 32;
    __shared__ float sg[32][33], su[32][33];
    const int tid = threadIdx.x;
    const int r = tid >> 3, cq = (tid & 7) * 4;
    {
        size_t off = ((size_t)e * HID + k0 + r) * INTER + n0 + cq;
        float4 vg = *reinterpret_cast<const float4*>(Wg + off);
        float4 vu = *reinterpret_cast<const float4*>(Wu + off);
        sg[r][cq + 0] = vg.x; sg[r][cq + 1] = vg.y; sg[r][cq + 2] = vg.z; sg[r][cq + 3] = vg.w;
        su[r][cq + 0] = vu.x; su[r][cq + 1] = vu.y; su[r][cq + 2] = vu.z; su[r][cq + 3] = vu.w;
    }
    __syncthreads();
    const int o = tid >> 2, c = (tid & 3) * 8;
    const int w = o & 15;
    const int nl = ((o >> 4) << 3) + (w & 7);
    const bool isU = (w >= 8);
    __align__(16) __half hh[8];
#pragma unroll
    for (int i = 0; i < 8; i++)
        hh[i] = __float2half(isU ? su[c + i][nl] : sg[c + i][nl]);
    *reinterpret_cast<uint4*>(&g_wgu[((size_t)e * 2 * INTER + n0 * 2 + o) * HID + k0 + c]) =
        *reinterpret_cast<uint4*>(hh);
}

// ---------------------------------------------------------------------------
// Wd [e][k=INTER][n=HID] -> g_wdt [e][n][k] fp16. tile: 32 k x 64 n, block 256
// ---------------------------------------------------------------------------
__global__ __launch_bounds__(256) void cvt_wd_kernel(const float* __restrict__ Wd) {
    const int e = blockIdx.z, k0 = blockIdx.y * 32, n0 = blockIdx.x * 64;
    __shared__ float sd[32][65];
    const int tid = threadIdx.x;
    const int r = tid >> 3, cq = (tid & 7) * 8;
    {
        size_t off = ((size_t)e * INTER + k0 + r) * HID + n0 + cq;
        float4 v0 = *reinterpret_cast<const float4*>(Wd + off);
        float4 v1 = *reinterpret_cast<const float4*>(Wd + off + 4);
        sd[r][cq + 0] = v0.x; sd[r][cq + 1] = v0.y; sd[r][cq + 2] = v0.z; sd[r][cq + 3] = v0.w;
        sd[r][cq + 4] = v1.x; sd[r][cq + 5] = v1.y; sd[r][cq + 6] = v1.z; sd[r][cq + 7] = v1.w;
    }
    __syncthreads();
    const int o = tid >> 2, c = (tid & 3) * 8;
    __align__(16) __half hh[8];
#pragma unroll
    for (int i = 0; i < 8; i++)
        hh[i] = __float2half(sd[c + i][o]);
    *reinterpret_cast<uint4*>(&g_wdt[((size_t)e * HID + n0 + o) * INTER + k0 + c]) =
        *reinterpret_cast<uint4*>(hh);
}

// ---------------------------------------------------------------------------
// router (exact fp32); packs slot bit into g_tok
// ---------------------------------------------------------------------------
__global__ __launch_bounds__(128) void router_kernel(const float* __restrict__ x,
                                                     const float* __restrict__ wgate) {
    const int t = blockIdx.x;
    const int tid = threadIdx.x;
    const float* xr = x + (size_t)t * HID;

    float part[NEXP];
#pragma unroll
    for (int e = 0; e < NEXP; e++) part[e] = 0.f;

    for (int h = tid * 4; h < HID; h += 128 * 4) {
        float4 xv = *reinterpret_cast<const float4*>(xr + h);
#pragma unroll
        for (int e = 0; e < NEXP; e++) {
            float4 wv = *reinterpret_cast<const float4*>(wgate + e * HID + h);
            part[e] += xv.x * wv.x + xv.y * wv.y + xv.z * wv.z + xv.w * wv.w;
        }
    }
#pragma unroll
    for (int e = 0; e < NEXP; e++)
#pragma unroll
        for (int o = 16; o > 0; o >>= 1)
            part[e] += __shfl_xor_sync(0xffffffffu, part[e], o);

    __shared__ float wsum[4][NEXP];
    const int warp = tid >> 5, lane = tid & 31;
    if (lane == 0)
#pragma unroll
        for (int e = 0; e < NEXP; e++) wsum[warp][e] = part[e];
    __syncthreads();

    if (tid == 0) {
        float logits[NEXP];
#pragma unroll
        for (int e = 0; e < NEXP; e++)
            logits[e] = wsum[0][e] + wsum[1][e] + wsum[2][e] + wsum[3][e];

        float mx = logits[0];
#pragma unroll
        for (int e = 1; e < NEXP; e++) mx = fmaxf(mx, logits[e]);
        float p[NEXP], s = 0.f;
#pragma unroll
        for (int e = 0; e < NEXP; e++) { p[e] = expf(logits[e] - mx); s += p[e]; }
        float inv = 1.f / s;
#pragma unroll
        for (int e = 0; e < NEXP; e++) p[e] *= inv;

        int e1 = 0;
#pragma unroll
        for (int e = 1; e < NEXP; e++) if (p[e] > p[e1]) e1 = e;
        int e2 = (e1 == 0) ? 1 : 0;
#pragma unroll
        for (int e = 0; e < NEXP; e++)
            if (e != e1 && p[e] > p[e2]) e2 = e;

        float w1 = p[e1], w2 = p[e2];
        float rs = 1.f / (w1 + w2);
        w1 *= rs; w2 *= rs;

        int s1 = atomicAdd(&g_cnt[e1], 1);
        g_tok[e1 * T_TOK + s1] = t * 2;         // slot 0
        g_wt [e1 * T_TOK + s1] = w1;
        int s2 = atomicAdd(&g_cnt[e2], 1);
        g_tok[e2 * T_TOK + s2] = t * 2 + 1;     // slot 1
        g_wt [e2 * T_TOK + s2] = w2;
    }
}

// ---------------------------------------------------------------------------
// gemm1: block 128m x 128ng (=64 logical n, g/u interleaved), 8 warps 64x32,
// 4-stage pure cp.async pipeline; silu(g)*u*w epilogue -> g_hc fp16
// ---------------------------------------------------------------------------
__global__ __launch_bounds__(256) void gemm1_kernel() {
    const int e = blockIdx.z;
    const int rows = g_cnt[e];
    const int m0 = blockIdx.y * 128;
    if (m0 >= rows) return;
    const int ngb = blockIdx.x * 128;
    const int n0l = blockIdx.x * 64;

    extern __shared__ __align__(16) __half dsm[];
    __half* sA = dsm;                   // 4 stages
    __half* sB = dsm + 4 * STAGE_H;     // 4 stages

    __shared__ int   stok[128];
    __shared__ float swt[128];

    const int tid = threadIdx.x;
    if (tid < 128) {
        int gm = m0 + tid;
        int idx = (gm < rows) ? gm : (rows - 1);
        stok[tid] = g_tok[e * T_TOK + idx] >> 1;
        swt [tid] = (gm < rows) ? g_wt[e * T_TOK + gm] : 0.f;
    }
    __syncthreads();

    const int lr = tid >> 1;             // loader row 0..127
    const int lo = (tid & 1) * 16;       // half-offset 0 or 16
    const __half* asrc = g_xh + (size_t)stok[lr] * HID + lo;
    const __half* bsrc = g_wgu + ((size_t)e * 2 * INTER + ngb + lr) * HID + lo;

    const int NT = HID / BK;   // 64

    auto issue = [&](int t) {
        if (t < NT) {
            __half* A = sA + (t & 3) * STAGE_H;
            __half* B = sB + (t & 3) * STAGE_H;
            int kk = t * BK;
            cp_async16(&A[lr * SAH + lo],     asrc + kk);
            cp_async16(&A[lr * SAH + lo + 8], asrc + kk + 8);
            cp_async16(&B[lr * SAH + lo],     bsrc + kk);
            cp_async16(&B[lr * SAH + lo + 8], bsrc + kk + 8);
        }
        CP_COMMIT();
    };

    issue(0); issue(1); issue(2);

    const int lane = tid & 31;
    const int warp = tid >> 5;
    const int wm = (warp & 1) * 64;
    const int wn = (warp >> 1) * 32;
    const int gid = lane >> 2, tg = lane & 3;

    float acc[4][4][4] = {};

    for (int t = 0; t < NT; t++) {
        CP_WAIT(2);
        __syncthreads();          // stage t visible; compute(t-1) done -> (t+3)&3 free
        issue(t + 3);

        const __half* A = sA + (t & 3) * STAGE_H;
        const __half* B = sB + (t & 3) * STAGE_H;

#pragma unroll
        for (int ks = 0; ks < BK; ks += 16) {
            unsigned a[4][4];
#pragma unroll
            for (int f = 0; f < 4; f++) {
                int r0 = wm + f * 16 + gid;
                a[f][0] = *reinterpret_cast<const unsigned*>(&A[(r0    ) * SAH + ks + 2 * tg    ]);
                a[f][1] = *reinterpret_cast<const unsigned*>(&A[(r0 + 8) * SAH + ks + 2 * tg    ]);
                a[f][2] = *reinterpret_cast<const unsigned*>(&A[(r0    ) * SAH + ks + 2 * tg + 8]);
                a[f][3] = *reinterpret_cast<const unsigned*>(&A[(r0 + 8) * SAH + ks + 2 * tg + 8]);
            }
            unsigned b[4][2];
#pragma unroll
            for (int j = 0; j < 4; j++) {
                int c = wn + j * 8 + gid;
                b[j][0] = *reinterpret_cast<const unsigned*>(&B[c * SAH + ks + 2 * tg    ]);
                b[j][1] = *reinterpret_cast<const unsigned*>(&B[c * SAH + ks + 2 * tg + 8]);
            }
#pragma unroll
            for (int f = 0; f < 4; f++)
#pragma unroll
                for (int j = 0; j < 4; j++)
                    mma_f16(acc[f][j], a[f], b[j]);
        }
    }

    // epilogue: j even = gate group, j odd = up group of same 8 logical cols
    __half* hbase = g_hc + (size_t)e * T_TOK * INTER;
#pragma unroll
    for (int f = 0; f < 4; f++) {
#pragma unroll
        for (int half = 0; half < 2; half++) {
            int rm = wm + f * 16 + half * 8 + gid;
            int gm = m0 + rm;
            if (gm < rows) {
                float w = swt[rm];
#pragma unroll
                for (int p = 0; p < 2; p++) {
                    float g0 = acc[f][2 * p    ][half * 2 + 0];
                    float g1 = acc[f][2 * p    ][half * 2 + 1];
                    float u0 = acc[f][2 * p + 1][half * 2 + 0];
                    float u1 = acc[f][2 * p + 1][half * 2 + 1];
                    float s0 = g0 / (1.f + expf(-g0)) * u0 * w;
                    float s1 = g1 / (1.f + expf(-g1)) * u1 * w;
                    int col = n0l + (wn >> 1) + p * 8 + 2 * tg;
                    *reinterpret_cast<__half2*>(hbase + (size_t)gm * INTER + col) =
                        __floats2half2_rn(s0, s1);
                }
            }
        }
    }
}

// ---------------------------------------------------------------------------
// gemm2: block 128m x 128n, 8 warps 64x32, 4-stage cp.async, STG to slot buf
// ---------------------------------------------------------------------------
__global__ __launch_bounds__(256) void gemm2_kernel() {
    const int e = blockIdx.z;
    const int rows = g_cnt[e];
    const int m0 = blockIdx.y * 128;
    if (m0 >= rows) return;
    const int n0 = blockIdx.x * 128;

    extern __shared__ __align__(16) __half dsm[];
    __half* sA = dsm;
    __half* sB = dsm + 4 * STAGE_H;

    __shared__ int stok[128];

    const int tid = threadIdx.x;
    if (tid < 128) {
        int gm = m0 + tid;
        int idx = (gm < rows) ? gm : (rows - 1);
        stok[tid] = g_tok[e * T_TOK + idx];   // packed
    }
    __syncthreads();

    const int lr = tid >> 1;
    const int lo = (tid & 1) * 16;
    int aidx = m0 + lr;
    if (aidx >= rows) aidx = rows - 1;
    const __half* asrc = g_hc + ((size_t)e * T_TOK + aidx) * INTER + lo;
    const __half* bsrc = g_wdt + ((size_t)e * HID + n0 + lr) * INTER + lo;

    const int NT = INTER / BK;   // 24

    auto issue = [&](int t) {
        if (t < NT) {
            __half* A = sA + (t & 3) * STAGE_H;
            __half* B = sB + (t & 3) * STAGE_H;
            int kk = t * BK;
            cp_async16(&A[lr * SAH + lo],     asrc + kk);
            cp_async16(&A[lr * SAH + lo + 8], asrc + kk + 8);
            cp_async16(&B[lr * SAH + lo],     bsrc + kk);
            cp_async16(&B[lr * SAH + lo + 8], bsrc + kk + 8);
        }
        CP_COMMIT();
    };

    issue(0); issue(1); issue(2);

    const int lane = tid & 31;
    const int warp = tid >> 5;
    const int wm = (warp & 1) * 64;
    const int wn = (warp >> 1) * 32;
    const int gid = lane >> 2, tg = lane & 3;

    float acc[4][4][4] = {};

    for (int t = 0; t < NT; t++) {
        CP_WAIT(2);
        __syncthreads();
        issue(t + 3);

        const __half* A = sA + (t & 3) * STAGE_H;
        const __half* B = sB + (t & 3) * STAGE_H;

#pragma unroll
        for (int ks = 0; ks < BK; ks += 16) {
            unsigned a[4][4];
#pragma unroll
            for (int f = 0; f < 4; f++) {
                int r0 = wm + f * 16 + gid;
                a[f][0] = *reinterpret_cast<const unsigned*>(&A[(r0    ) * SAH + ks + 2 * tg    ]);
                a[f][1] = *reinterpret_cast<const unsigned*>(&A[(r0 + 8) * SAH + ks + 2 * tg    ]);
                a[f][2] = *reinterpret_cast<const unsigned*>(&A[(r0    ) * SAH + ks + 2 * tg + 8]);
                a[f][3] = *reinterpret_cast<const unsigned*>(&A[(r0 + 8) * SAH + ks + 2 * tg + 8]);
            }
            unsigned b[4][2];
#pragma unroll
            for (int j = 0; j < 4; j++) {
                int c = wn + j * 8 + gid;
                b[j][0] = *reinterpret_cast<const unsigned*>(&B[c * SAH + ks + 2 * tg    ]);
                b[j][1] = *reinterpret_cast<const unsigned*>(&B[c * SAH + ks + 2 * tg + 8]);
            }
#pragma unroll
            for (int f = 0; f < 4; f++)
#pragma unroll
                for (int j = 0; j < 4; j++)
                    mma_f16(acc[f][j], a[f], b[j]);
        }
    }

#pragma unroll
    for (int f = 0; f < 4; f++) {
#pragma unroll
        for (int half = 0; half < 2; half++) {
            int rm = wm + f * 16 + half * 8 + gid;
            int gm = m0 + rm;
            if (gm < rows) {
                int v = stok[rm];
                float* orow = g_y + (size_t)(v & 1) * T_TOK * HID + (size_t)(v >> 1) * HID + n0;
#pragma unroll
                for (int j = 0; j < 4; j++) {
                    int col = wn + j * 8 + 2 * tg;
                    *reinterpret_cast<float2*>(orow + col) =
                        make_float2(acc[f][j][half * 2 + 0], acc[f][j][half * 2 + 1]);
                }
            }
        }
    }
}

// ---------------------------------------------------------------------------
// combine: out = y_slot0 + y_slot1 (fully overwrites out)
// ---------------------------------------------------------------------------
__global__ void combine_kernel(float* __restrict__ out) {
    int i = blockIdx.x * blockDim.x + threadIdx.x;
    float4 a = reinterpret_cast<const float4*>(g_y)[i];
    float4 b = reinterpret_cast<const float4*>(g_y + (size_t)T_TOK * HID)[i];
    reinterpret_cast<float4*>(out)[i] = make_float4(a.x + b.x, a.y + b.y, a.z + b.z, a.w + b.w);
}

// ---------------------------------------------------------------------------
extern "C" void kernel_launch(void* const* d_in, const int* in_sizes, int n_in,
                              void* d_out, int out_size) {
    const float* x     = (const float*)d_in[0];
    const float* wgate = (const float*)d_in[1];
    const float* Wg    = (const float*)d_in[2];
    const float* Wu    = (const float*)d_in[3];
    const float* Wd    = (const float*)d_in[4];
    float* out = (float*)d_out;

    const int gsmem = 8 * STAGE_H * (int)sizeof(__half);   // 81920
    cudaFuncSetAttribute(gemm1_kernel, cudaFuncAttributeMaxDynamicSharedMemorySize, gsmem);
    cudaFuncSetAttribute(gemm2_kernel, cudaFuncAttributeMaxDynamicSharedMemorySize, gsmem);

    cvt_x_kernel<<<(T_TOK * HID / 8 + 255) / 256, 256>>>(x);
    cvt_wgu_kernel<<<dim3(INTER / 32, HID / 32, NEXP), 256>>>(Wg, Wu);
    cvt_wd_kernel<<<dim3(HID / 64, INTER / 32, NEXP), 256>>>(Wd);

    router_kernel<<<T_TOK, 128>>>(x, wgate);

    gemm1_kernel<<<dim3(INTER / 64, T_TOK / 128, NEXP), 256, gsmem>>>();
    gemm2_kernel<<<dim3(HID / 128, T_TOK / 128, NEXP), 256, gsmem>>>();

    combine_kernel<<<(T_TOK * HID / 4 + 255) / 256, 256>>>(out);
}